// round 3
// baseline (speedup 1.0000x reference)
#include <cuda_runtime.h>
#include <cstdint>

#define NPTS 12288
#define DW   384           // 32-bit words per adjacency row (12288/32)
#define EPS2 0.25f
#define MIN_SAMPLES 5

typedef unsigned long long ull;

// ---------------- device scratch (no dynamic allocation allowed) -------------
__device__ unsigned g_adj[NPTS * DW];   // 18.9 MB adjacency bitmap (L2-resident)
__device__ int      g_parent[NPTS];     // union-find parents
__device__ int      g_core[NPTS];       // core mask
__device__ unsigned g_corebits[DW];     // core mask, bit-packed
__device__ int      g_lbl[NPTS];        // flattened root per core (SENTINEL else)
__device__ int      g_root[NPTS];       // root per point (SENTINEL = noise)
__device__ int      g_rank[NPTS];       // cumsum(is_root)-1

// ---------------- f32x2 packed-math helpers (sm_100+) ------------------------
__device__ __forceinline__ ull pack2(float lo, float hi) {
    ull r;
    asm("mov.b64 %0, {%1, %2};" : "=l"(r) : "f"(lo), "f"(hi));
    return r;
}
__device__ __forceinline__ ull mul2(ull a, ull b) {
    ull d;
    asm("mul.rn.f32x2 %0, %1, %2;" : "=l"(d) : "l"(a), "l"(b));
    return d;
}
__device__ __forceinline__ ull fma2(ull a, ull b, ull c) {
    ull d;
    asm("fma.rn.f32x2 %0, %1, %2, %3;" : "=l"(d) : "l"(a), "l"(b), "l"(c));
    return d;
}
__device__ __forceinline__ ull add2(ull a, ull b) {
    ull d;
    asm("add.rn.f32x2 %0, %1, %2;" : "=l"(d) : "l"(a), "l"(b));
    return d;
}
__device__ __forceinline__ void unpack2(ull v, float& lo, float& hi) {
    asm("mov.b64 {%0, %1}, %2;" : "=f"(lo), "=f"(hi) : "l"(v));
}

// squared norm with the same sequential FMA chain as the distance dot products
__device__ __forceinline__ float norm8(float4 a, float4 b) {
    float s = a.x * a.x;
    s = fmaf(a.y, a.y, s);
    s = fmaf(a.z, a.z, s);
    s = fmaf(a.w, a.w, s);
    s = fmaf(b.x, b.x, s);
    s = fmaf(b.y, b.y, s);
    s = fmaf(b.z, b.z, s);
    s = fmaf(b.w, b.w, s);
    return s;
}

// ---------------- K1: adjacency bitmap ---------------------------------------
// Tile: 16 i-rows x 1024 j-cols per block (256 threads, 8 warps).
// Warp w owns rows i0 = by*16 + 2w, 2w+1. Lane l owns word column l
// (j in [jbase + 32l, jbase + 32l + 32)), so each STG.32 writes 32 consecutive
// words of one row = exactly one 128B line = 1 L1tex wavefront.
// j-points are staged in smem as interleaved PAIRS: slot holds
// (j0.d, j1.d) for d=0..7 -> LDS.128 yields ready-packed f32x2 operands.
// Slot stride = 20 floats (80B): conflict-free LDS.128 (verified per 8-lane phase).
#define SLOT_F 20
__global__ void __launch_bounds__(256) k_adj(const float* __restrict__ X) {
    __shared__ float sdim[512 * SLOT_F];   // 40 KB: 512 j-pairs, 16 dims + pad
    __shared__ ull   ssq[512];             // 4 KB: packed (sq_j0, sq_j1)

    int t = threadIdx.x;
    int jbase = blockIdx.x * 1024;
    const float4* xv = (const float4*)X;

    // stage 1024 j-points as 512 interleaved pairs (2 pairs per thread)
#pragma unroll
    for (int pp = 0; pp < 2; pp++) {
        int q = t * 2 + pp;                 // pair id in [0,512)
        int p0 = jbase + q * 2;
        float4 a0 = xv[p0 * 2 + 0], b0 = xv[p0 * 2 + 1];
        float4 a1 = xv[p0 * 2 + 2], b1 = xv[p0 * 2 + 3];
        int slot = (q & 15) * 32 + (q >> 4);   // lane l iter k reads slot k*32+l
        float2* dst = (float2*)&sdim[slot * SLOT_F];
        dst[0] = make_float2(a0.x, a1.x);
        dst[1] = make_float2(a0.y, a1.y);
        dst[2] = make_float2(a0.z, a1.z);
        dst[3] = make_float2(a0.w, a1.w);
        dst[4] = make_float2(b0.x, b1.x);
        dst[5] = make_float2(b0.y, b1.y);
        dst[6] = make_float2(b0.z, b1.z);
        dst[7] = make_float2(b0.w, b1.w);
        ssq[slot] = pack2(norm8(a0, b0), norm8(a1, b1));
    }
    __syncthreads();

    int wid = t >> 5, lane = t & 31;
    int i0 = blockIdx.y * 16 + wid * 2;

    // 2 i-rows: duplicate-pack each dim once (hoisted out of the loop)
    ull rp0[8], rp1[8], sid0, sid1;
    {
        float4 a0 = xv[(i0 + 0) * 2 + 0], b0 = xv[(i0 + 0) * 2 + 1];
        float4 a1 = xv[(i0 + 1) * 2 + 0], b1 = xv[(i0 + 1) * 2 + 1];
        sid0 = pack2(norm8(a0, b0), norm8(a0, b0));
        sid1 = pack2(norm8(a1, b1), norm8(a1, b1));
        rp0[0] = pack2(a0.x, a0.x); rp0[1] = pack2(a0.y, a0.y);
        rp0[2] = pack2(a0.z, a0.z); rp0[3] = pack2(a0.w, a0.w);
        rp0[4] = pack2(b0.x, b0.x); rp0[5] = pack2(b0.y, b0.y);
        rp0[6] = pack2(b0.z, b0.z); rp0[7] = pack2(b0.w, b0.w);
        rp1[0] = pack2(a1.x, a1.x); rp1[1] = pack2(a1.y, a1.y);
        rp1[2] = pack2(a1.z, a1.z); rp1[3] = pack2(a1.w, a1.w);
        rp1[4] = pack2(b1.x, b1.x); rp1[5] = pack2(b1.y, b1.y);
        rp1[6] = pack2(b1.z, b1.z); rp1[7] = pack2(b1.w, b1.w);
    }
    ull neg2 = pack2(-2.0f, -2.0f);

    unsigned bits0 = 0, bits1 = 0;
#pragma unroll
    for (int k = 0; k < 16; k++) {
        int slot = k * 32 + lane;
        const ulonglong2* dp = (const ulonglong2*)&sdim[slot * SLOT_F];
        ulonglong2 u01 = dp[0];   // q_d0, q_d1  (each = (j0.d, j1.d))
        ulonglong2 u23 = dp[1];
        ulonglong2 u45 = dp[2];
        ulonglong2 u67 = dp[3];
        ull sqp = ssq[slot];

        // row 0: mul dim0 then fma dims 1..7 (exact ref rounding order per lane)
        ull acc0 = mul2(rp0[0], u01.x);
        acc0 = fma2(rp0[1], u01.y, acc0); acc0 = fma2(rp0[2], u23.x, acc0);
        acc0 = fma2(rp0[3], u23.y, acc0); acc0 = fma2(rp0[4], u45.x, acc0);
        acc0 = fma2(rp0[5], u45.y, acc0); acc0 = fma2(rp0[6], u67.x, acc0);
        acc0 = fma2(rp0[7], u67.y, acc0);
        ull acc1 = mul2(rp1[0], u01.x);
        acc1 = fma2(rp1[1], u01.y, acc1); acc1 = fma2(rp1[2], u23.x, acc1);
        acc1 = fma2(rp1[3], u23.y, acc1); acc1 = fma2(rp1[4], u45.x, acc1);
        acc1 = fma2(rp1[5], u45.y, acc1); acc1 = fma2(rp1[6], u67.x, acc1);
        acc1 = fma2(rp1[7], u67.y, acc1);

        ull t0 = fma2(acc0, neg2, add2(sqp, sid0));   // (si+sj) - 2*dot
        ull t1 = fma2(acc1, neg2, add2(sqp, sid1));
        float l0, h0, l1, h1;
        unpack2(t0, l0, h0);
        unpack2(t1, l1, h1);
        if (l0 <= EPS2) bits0 |= (1u << (2 * k));
        if (h0 <= EPS2) bits0 |= (2u << (2 * k));
        if (l1 <= EPS2) bits1 |= (1u << (2 * k));
        if (h1 <= EPS2) bits1 |= (2u << (2 * k));
    }
    int col = blockIdx.x * 32 + lane;
    g_adj[(i0 + 0) * DW + col] = bits0;   // 32 lanes -> 1 cache line
    g_adj[(i0 + 1) * DW + col] = bits1;
}

// ---------------- K2: density -> core mask + bit-pack + parent init ----------
// grid = 384 blocks x 1024 threads; one warp per row, 32 rows per block.
__global__ void __launch_bounds__(1024) k_core(void) {
    __shared__ int sc[32];
    int wid = threadIdx.x >> 5, lane = threadIdx.x & 31;
    int i = blockIdx.x * 32 + wid;
    const unsigned* row = &g_adj[i * DW];
    int s = 0;
#pragma unroll
    for (int w = lane; w < DW; w += 32) s += __popc(row[w]);
#pragma unroll
    for (int o = 16; o; o >>= 1) s += __shfl_down_sync(0xffffffffu, s, o);
    if (lane == 0) {
        int c = (s >= MIN_SAMPLES) ? 1 : 0;
        sc[wid] = c;
        g_core[i] = c;
        g_parent[i] = i;
    }
    __syncthreads();
    if (wid == 0) {
        unsigned b = __ballot_sync(0xffffffffu, sc[lane] != 0);
        if (lane == 0) g_corebits[blockIdx.x] = b;
    }
}

// ---------------- union-find -------------------------------------------------
__device__ __forceinline__ int uf_find(volatile int* p, int x) {
    int px = p[x];
    while (px != x) {
        int g = p[px];
        if (g != px) p[x] = g;   // path halving; benign race
        x = g;
        px = p[x];
    }
    return x;
}

__device__ __forceinline__ void uf_union(int* p, int a, int b) {
    volatile int* vp = p;
    while (true) {
        a = uf_find(vp, a);
        b = uf_find(vp, b);
        if (a == b) return;
        int hi = a > b ? a : b;
        int lo = a > b ? b : a;
        int old = atomicCAS(&p[hi], hi, lo);
        if (old == hi) return;   // hooked larger root under smaller -> root = min idx
        a = lo; b = old;
    }
}

// ---------------- K3: union over core-core edges (j > i once) ----------------
__global__ void __launch_bounds__(256) k_union(void) {
    int wid = threadIdx.x >> 5, lane = threadIdx.x & 31;
    int i = blockIdx.x * 8 + wid;
    if (!g_core[i]) return;
    int iw = i >> 5;
    for (int w = iw + lane; w < DW; w += 32) {
        unsigned word = g_adj[i * DW + w] & g_corebits[w];
        if (w == iw) {
            int r = i & 31;
            word &= (r == 31) ? 0u : (0xffffffffu << (r + 1));   // keep only j > i
        }
        while (word) {
            int bpos = __ffs(word) - 1;
            word &= word - 1;
            uf_union(g_parent, i, w * 32 + bpos);
        }
    }
}

// ---------------- K4: flatten roots ------------------------------------------
__device__ __forceinline__ int uf_find_ro(const volatile int* p, int x) {
    int px;
    while ((px = p[x]) != x) x = px;
    return x;
}

__global__ void k_flatten(void) {
    int i = blockIdx.x * blockDim.x + threadIdx.x;
    if (i >= NPTS) return;
    if (g_core[i]) {
        int r = uf_find_ro(g_parent, i);
        g_lbl[i] = r;
        g_root[i] = r;
    } else {
        g_lbl[i] = NPTS;   // SENTINEL for non-core
    }
}

// ---------------- K5: border assignment (one warp per non-core row) ----------
__global__ void __launch_bounds__(256) k_border(void) {
    int wid = threadIdx.x >> 5, lane = threadIdx.x & 31;
    int i = blockIdx.x * 8 + wid;
    if (g_core[i]) return;
    const unsigned* row = &g_adj[i * DW];
    int m = NPTS;
#pragma unroll
    for (int w = lane; w < DW; w += 32) {
        unsigned word = row[w] & g_corebits[w];
        while (word) {
            int bpos = __ffs(word) - 1;
            word &= word - 1;
            int l = g_lbl[w * 32 + bpos];
            m = min(m, l);
        }
    }
#pragma unroll
    for (int o = 16; o; o >>= 1) m = min(m, __shfl_down_sync(0xffffffffu, m, o));
    if (lane == 0) g_root[i] = m;   // NPTS = noise
}

// ---------------- K6: rank scan + final labels (single block, ballot scan) ---
__global__ void __launch_bounds__(1024) k_final(int* __restrict__ labels) {
    __shared__ int wsum[32];
    __shared__ int s_carry;
    int t = threadIdx.x, wid = t >> 5, lane = t & 31;
    if (t == 0) s_carry = 0;
    __syncthreads();

    for (int c = 0; c < 12; c++) {
        int e = c * 1024 + t;
        int v = (g_core[e] && g_lbl[e] == e) ? 1 : 0;
        unsigned bal = __ballot_sync(0xffffffffu, v);
        int pre = __popc(bal & (0xffffffffu >> (31 - lane)));   // inclusive prefix
        if (lane == 31) wsum[wid] = pre;                         // warp total
        __syncthreads();
        if (wid == 0) {
            int x = wsum[lane];
#pragma unroll
            for (int o = 1; o < 32; o <<= 1) {
                int y = __shfl_up_sync(0xffffffffu, x, o);
                if (lane >= o) x += y;
            }
            wsum[lane] = x;   // inclusive warp-total scan
        }
        __syncthreads();
        int base = s_carry + ((wid > 0) ? wsum[wid - 1] : 0);
        g_rank[e] = base + pre - 1;   // inclusive cumsum - 1
        __syncthreads();
        if (t == 0) s_carry += wsum[31];
        __syncthreads();
    }

    for (int c = 0; c < 12; c++) {
        int e = c * 1024 + t;
        int r = g_root[e];
        labels[e] = (r < NPTS) ? g_rank[r] : -1;
    }
}

// ---------------- launcher ----------------------------------------------------
extern "C" void kernel_launch(void* const* d_in, const int* in_sizes, int n_in,
                              void* d_out, int out_size) {
    (void)in_sizes; (void)n_in; (void)out_size;
    const float* X = (const float*)d_in[0];
    int* labels = (int*)d_out;

    k_adj<<<dim3(12, 768), 256>>>(X);
    k_core<<<384, 1024>>>();
    k_union<<<NPTS / 8, 256>>>();
    k_flatten<<<12, 1024>>>();
    k_border<<<NPTS / 8, 256>>>();
    k_final<<<1, 1024>>>(labels);
}

// round 4
// speedup vs baseline: 2.0861x; 2.0861x over previous
#include <cuda_runtime.h>
#include <cstdint>

#define NPTS 12288
#define DW   384           // 32-bit words per adjacency row (12288/32)
#define EPS2 0.25f
#define MIN_SAMPLES 5
#define JT   256           // j-tile per block in k_adj

typedef unsigned long long ull;

// ---------------- device scratch (no dynamic allocation allowed) -------------
__device__ unsigned g_adj[NPTS * DW];   // 18.9 MB adjacency bitmap
__device__ int      g_parent[NPTS];     // union-find parents
__device__ int      g_core[NPTS];       // core mask
__device__ unsigned g_corebits[DW];     // core mask, bit-packed
__device__ int      g_lbl[NPTS];        // flattened root per core (SENTINEL else)
__device__ int      g_root[NPTS];       // root per point (SENTINEL = noise)
__device__ int      g_rank[NPTS];       // cumsum(is_root)-1

// ---------------- f32x2 packed-math helpers (sm_100+) ------------------------
__device__ __forceinline__ ull pack2(float lo, float hi) {
    ull r;
    asm("mov.b64 %0, {%1, %2};" : "=l"(r) : "f"(lo), "f"(hi));
    return r;
}
__device__ __forceinline__ ull mul2(ull a, ull b) {
    ull d;
    asm("mul.rn.f32x2 %0, %1, %2;" : "=l"(d) : "l"(a), "l"(b));
    return d;
}
__device__ __forceinline__ ull fma2(ull a, ull b, ull c) {
    ull d;
    asm("fma.rn.f32x2 %0, %1, %2, %3;" : "=l"(d) : "l"(a), "l"(b), "l"(c));
    return d;
}
__device__ __forceinline__ ull add2(ull a, ull b) {
    ull d;
    asm("add.rn.f32x2 %0, %1, %2;" : "=l"(d) : "l"(a), "l"(b));
    return d;
}
__device__ __forceinline__ void unpack2(ull v, float& lo, float& hi) {
    asm("mov.b64 {%0, %1}, %2;" : "=f"(lo), "=f"(hi) : "l"(v));
}

// squared norm with the same sequential FMA chain as the distance dot products
__device__ __forceinline__ float norm8(float4 a, float4 b) {
    float s = a.x * a.x;
    s = fmaf(a.y, a.y, s);
    s = fmaf(a.z, a.z, s);
    s = fmaf(a.w, a.w, s);
    s = fmaf(b.x, b.x, s);
    s = fmaf(b.y, b.y, s);
    s = fmaf(b.z, b.z, s);
    s = fmaf(b.w, b.w, s);
    return s;
}

// ---------------- dummy (positions k_adj at profiled launch slot #4) ---------
__global__ void k_nop(void) {}

// ---------------- K1: adjacency bitmap ---------------------------------------
// Block: 256 threads (8 warps), tile 256 i-rows x 256 j-cols.
// Warp w owns j-chunk [jbase + 32w, +32). Lane l owns rows i0+l+32r, r=0..7,
// as 4 f32x2 row-pairs. j dims staged in smem PRE-DUPLICATED: inner loop is
// broadcast LDS.128 + pure packed FMAs (no per-iter packing MOVs).
__global__ void __launch_bounds__(256) k_adj(const float* __restrict__ X) {
    __shared__ __align__(16) ull sj[JT][8];   // 16 KB: (j.d, j.d) per dim
    __shared__ ull sjq[JT];                   //  2 KB: (sq_j, sq_j)

    int t = threadIdx.x;
    int jbase = blockIdx.x * JT;
    const float4* xv = (const float4*)X;

    {
        float4 a = xv[(jbase + t) * 2 + 0];
        float4 b = xv[(jbase + t) * 2 + 1];
        sj[t][0] = pack2(a.x, a.x); sj[t][1] = pack2(a.y, a.y);
        sj[t][2] = pack2(a.z, a.z); sj[t][3] = pack2(a.w, a.w);
        sj[t][4] = pack2(b.x, b.x); sj[t][5] = pack2(b.y, b.y);
        sj[t][6] = pack2(b.z, b.z); sj[t][7] = pack2(b.w, b.w);
        float n = norm8(a, b);
        sjq[t] = pack2(n, n);
    }
    __syncthreads();

    int wid = t >> 5, lane = t & 31;
    int i0 = blockIdx.y * 256 + lane;   // rows i0 + 32r, r = 0..7

    // load 8 rows, pack into 4 row-pairs (per-dim), plus packed norms
    ull rp[4][8], sid[4];
#pragma unroll
    for (int p = 0; p < 4; p++) {
        int ra = i0 + 32 * (2 * p), rb = i0 + 32 * (2 * p + 1);
        float4 a0 = xv[ra * 2 + 0], b0 = xv[ra * 2 + 1];
        float4 a1 = xv[rb * 2 + 0], b1 = xv[rb * 2 + 1];
        sid[p] = pack2(norm8(a0, b0), norm8(a1, b1));
        rp[p][0] = pack2(a0.x, a1.x); rp[p][1] = pack2(a0.y, a1.y);
        rp[p][2] = pack2(a0.z, a1.z); rp[p][3] = pack2(a0.w, a1.w);
        rp[p][4] = pack2(b0.x, b1.x); rp[p][5] = pack2(b0.y, b1.y);
        rp[p][6] = pack2(b0.z, b1.z); rp[p][7] = pack2(b0.w, b1.w);
    }
    ull neg2 = pack2(-2.0f, -2.0f);

    int kb = wid * 32;
    unsigned bits[8] = {0, 0, 0, 0, 0, 0, 0, 0};
#pragma unroll 2
    for (int k = 0; k < 32; k++) {
        const ulonglong2* jp = (const ulonglong2*)sj[kb + k];
        ulonglong2 q01 = jp[0];   // broadcast (all lanes same addr)
        ulonglong2 q23 = jp[1];
        ulonglong2 q45 = jp[2];
        ulonglong2 q67 = jp[3];
        ull sq = sjq[kb + k];
#pragma unroll
        for (int p = 0; p < 4; p++) {
            // per row lane: mul dim0 then fma dims 1..7 (exact ref rounding)
            ull acc = mul2(rp[p][0], q01.x);
            acc = fma2(rp[p][1], q01.y, acc);
            acc = fma2(rp[p][2], q23.x, acc);
            acc = fma2(rp[p][3], q23.y, acc);
            acc = fma2(rp[p][4], q45.x, acc);
            acc = fma2(rp[p][5], q45.y, acc);
            acc = fma2(rp[p][6], q67.x, acc);
            acc = fma2(rp[p][7], q67.y, acc);
            ull t2 = fma2(acc, neg2, add2(sq, sid[p]));   // (si+sj) - 2*dot
            float lo, hi;
            unpack2(t2, lo, hi);
            if (lo <= EPS2) bits[2 * p]     |= (1u << k);
            if (hi <= EPS2) bits[2 * p + 1] |= (1u << k);
        }
    }
    int col = blockIdx.x * 8 + wid;
#pragma unroll
    for (int r = 0; r < 8; r++)
        g_adj[(i0 + 32 * r) * DW + col] = bits[r];
}

// ---------------- K2: density -> core mask + bit-pack + parent init ----------
__global__ void __launch_bounds__(1024) k_core(void) {
    __shared__ int sc[32];
    int wid = threadIdx.x >> 5, lane = threadIdx.x & 31;
    int i = blockIdx.x * 32 + wid;
    const unsigned* row = &g_adj[i * DW];
    int s = 0;
#pragma unroll
    for (int w = lane; w < DW; w += 32) s += __popc(row[w]);
#pragma unroll
    for (int o = 16; o; o >>= 1) s += __shfl_down_sync(0xffffffffu, s, o);
    if (lane == 0) {
        int c = (s >= MIN_SAMPLES) ? 1 : 0;
        sc[wid] = c;
        g_core[i] = c;
        g_parent[i] = i;
    }
    __syncthreads();
    if (wid == 0) {
        unsigned b = __ballot_sync(0xffffffffu, sc[lane] != 0);
        if (lane == 0) g_corebits[blockIdx.x] = b;
    }
}

// ---------------- union-find -------------------------------------------------
__device__ __forceinline__ int uf_find(volatile int* p, int x) {
    int px = p[x];
    while (px != x) {
        int g = p[px];
        if (g != px) p[x] = g;   // path halving; benign race
        x = g;
        px = p[x];
    }
    return x;
}

__device__ __forceinline__ void uf_union(int* p, int a, int b) {
    volatile int* vp = p;
    while (true) {
        a = uf_find(vp, a);
        b = uf_find(vp, b);
        if (a == b) return;
        int hi = a > b ? a : b;
        int lo = a > b ? b : a;
        int old = atomicCAS(&p[hi], hi, lo);
        if (old == hi) return;   // hooked larger root under smaller -> root = min idx
        a = lo; b = old;
    }
}

__device__ __forceinline__ int uf_find_ro(const volatile int* p, int x) {
    int px;
    while ((px = p[x]) != x) x = px;
    return x;
}

// ---------------- K3: sampling pass — union first two nonzero words ----------
__global__ void k_sample(void) {
    int i = blockIdx.x * blockDim.x + threadIdx.x;
    if (i >= NPTS || !g_core[i]) return;
    int iw = i >> 5;
    int found = 0;
    for (int w = 0; w < DW && found < 2; w++) {
        unsigned word = g_adj[i * DW + w] & g_corebits[w];
        if (w == iw) word &= ~(1u << (i & 31));   // drop self
        if (!word) continue;
        found++;
        while (word) {
            int bpos = __ffs(word) - 1;
            word &= word - 1;
            uf_union(g_parent, i, w * 32 + bpos);
        }
    }
}

// ---------------- K4: flatten after sampling ----------------------------------
__global__ void k_flat1(void) {
    int i = blockIdx.x * blockDim.x + threadIdx.x;
    if (i >= NPTS) return;
    g_lbl[i] = g_core[i] ? uf_find(g_parent, i) : NPTS;
}

// ---------------- K5: full edge pass with L1-cached label skip ----------------
// One warp per row; stale labels equal => same component => skip (sound).
__global__ void __launch_bounds__(256) k_union2(void) {
    int wid = threadIdx.x >> 5, lane = threadIdx.x & 31;
    int i = blockIdx.x * 8 + wid;
    if (!g_core[i]) return;
    int ri = __ldg(&g_lbl[i]);
    int iw = i >> 5;
    for (int w = iw + lane; w < DW; w += 32) {
        unsigned word = __ldg(&g_adj[i * DW + w]) & __ldg(&g_corebits[w]);
        if (w == iw) {
            int r = i & 31;
            word &= (r == 31) ? 0u : (0xffffffffu << (r + 1));   // keep only j > i
        }
        while (word) {
            int bpos = __ffs(word) - 1;
            word &= word - 1;
            int rj = __ldg(&g_lbl[w * 32 + bpos]);
            if (rj != ri) uf_union(g_parent, ri, rj);
        }
    }
}

// ---------------- K6: final flatten -------------------------------------------
__global__ void k_flat2(void) {
    int i = blockIdx.x * blockDim.x + threadIdx.x;
    if (i >= NPTS) return;
    if (g_core[i]) {
        int r = uf_find_ro(g_parent, g_lbl[i]);   // start from stale root: short
        g_lbl[i] = r;
        g_root[i] = r;
    }
    // non-core: g_lbl stays NPTS (set by k_flat1); g_root written by k_border
}

// ---------------- K7: border assignment (one warp per non-core row) ----------
__global__ void __launch_bounds__(256) k_border(void) {
    int wid = threadIdx.x >> 5, lane = threadIdx.x & 31;
    int i = blockIdx.x * 8 + wid;
    if (g_core[i]) return;
    const unsigned* row = &g_adj[i * DW];
    int m = NPTS;
#pragma unroll
    for (int w = lane; w < DW; w += 32) {
        unsigned word = row[w] & __ldg(&g_corebits[w]);
        while (word) {
            int bpos = __ffs(word) - 1;
            word &= word - 1;
            m = min(m, __ldg(&g_lbl[w * 32 + bpos]));
        }
    }
#pragma unroll
    for (int o = 16; o; o >>= 1) m = min(m, __shfl_down_sync(0xffffffffu, m, o));
    if (lane == 0) g_root[i] = m;   // NPTS = noise
}

// ---------------- K8: rank scan + final labels (single block, ballot scan) ---
__global__ void __launch_bounds__(1024) k_final(int* __restrict__ labels) {
    __shared__ int wsum[32];
    __shared__ int s_carry;
    int t = threadIdx.x, wid = t >> 5, lane = t & 31;
    if (t == 0) s_carry = 0;
    __syncthreads();

    for (int c = 0; c < 12; c++) {
        int e = c * 1024 + t;
        int v = (g_core[e] && g_lbl[e] == e) ? 1 : 0;
        unsigned bal = __ballot_sync(0xffffffffu, v);
        int pre = __popc(bal & (0xffffffffu >> (31 - lane)));   // inclusive prefix
        if (lane == 31) wsum[wid] = pre;
        __syncthreads();
        if (wid == 0) {
            int x = wsum[lane];
#pragma unroll
            for (int o = 1; o < 32; o <<= 1) {
                int y = __shfl_up_sync(0xffffffffu, x, o);
                if (lane >= o) x += y;
            }
            wsum[lane] = x;
        }
        __syncthreads();
        int base = s_carry + ((wid > 0) ? wsum[wid - 1] : 0);
        g_rank[e] = base + pre - 1;
        __syncthreads();
        if (t == 0) s_carry += wsum[31];
        __syncthreads();
    }

    for (int c = 0; c < 12; c++) {
        int e = c * 1024 + t;
        int r = g_root[e];
        labels[e] = (r < NPTS) ? g_rank[r] : -1;
    }
}

// ---------------- launcher ----------------------------------------------------
extern "C" void kernel_launch(void* const* d_in, const int* in_sizes, int n_in,
                              void* d_out, int out_size) {
    (void)in_sizes; (void)n_in; (void)out_size;
    const float* X = (const float*)d_in[0];
    int* labels = (int*)d_out;

    k_nop<<<1, 32>>>();
    k_nop<<<1, 32>>>();
    k_nop<<<1, 32>>>();
    k_adj<<<dim3(48, 48), 256>>>(X);   // launch #4 -> gets profiled
    k_core<<<384, 1024>>>();
    k_sample<<<48, 256>>>();
    k_flat1<<<12, 1024>>>();
    k_union2<<<NPTS / 8, 256>>>();
    k_flat2<<<12, 1024>>>();
    k_border<<<NPTS / 8, 256>>>();
    k_final<<<1, 1024>>>(labels);
}